// round 3
// baseline (speedup 1.0000x reference)
#include <cuda_runtime.h>
#include <cstdint>

#define Bsz 2
#define Ssz 1024
#define Dm  1024
#define Hh  16
#define DKk 64
#define Ff  4096
#define Vv  32000
#define Ll  8
#define TOK (Bsz*Ssz)

// ---------------- scratch (static device globals: allocation-free) ----------
__device__ float g_x [TOK*Dm];
__device__ float g_h [TOK*Dm];
__device__ float g_q [TOK*Dm];
__device__ float g_k [TOK*Dm];
__device__ float g_v [TOK*Dm];
__device__ float g_o [TOK*Dm];
__device__ float g_ff[TOK*Ff];
__device__ float g_sc[(size_t)Bsz*Hh*Ssz*Ssz];   // 128 MB

// ---------------- embedding: x = tok_emb[ids] + pos_emb[:S] -----------------
__global__ __launch_bounds__(256) void embed_k(
    const int* __restrict__ ids, const float* __restrict__ tok,
    const float* __restrict__ pos, float* __restrict__ x)
{
    const int row = blockIdx.x;            // 0..TOK-1
    const int s   = row & (Ssz - 1);
    const int id  = ids[row];
    const int t   = threadIdx.x;           // 256 threads, 4 floats each
    float4 tv = *(const float4*)(tok + (size_t)id * Dm + t * 4);
    float4 pv = *(const float4*)(pos + (size_t)s  * Dm + t * 4);
    float4 o; o.x = tv.x + pv.x; o.y = tv.y + pv.y; o.z = tv.z + pv.z; o.w = tv.w + pv.w;
    *(float4*)(x + (size_t)row * Dm + t * 4) = o;
}

// ---------------- layernorm (one block per row, D=1024) ---------------------
__global__ __launch_bounds__(256) void layernorm_k(
    const float* __restrict__ x, const float* __restrict__ g,
    const float* __restrict__ be, float* __restrict__ out)
{
    const int row = blockIdx.x;
    const int t   = threadIdx.x;
    const float* xr = x + (size_t)row * Dm;
    float4 v = *(const float4*)(xr + t * 4);
    float s  = v.x + v.y + v.z + v.w;
    float ss = v.x*v.x + v.y*v.y + v.z*v.z + v.w*v.w;
    #pragma unroll
    for (int off = 16; off; off >>= 1) {
        s  += __shfl_xor_sync(0xffffffffu, s,  off);
        ss += __shfl_xor_sync(0xffffffffu, ss, off);
    }
    __shared__ float rs[8], rss[8];
    const int warp = t >> 5, lane = t & 31;
    if (lane == 0) { rs[warp] = s; rss[warp] = ss; }
    __syncthreads();
    s = 0.f; ss = 0.f;
    #pragma unroll
    for (int i = 0; i < 8; i++) { s += rs[i]; ss += rss[i]; }
    const float mean = s  * (1.0f / Dm);
    const float var  = ss * (1.0f / Dm) - mean * mean;
    const float rstd = rsqrtf(var + 1e-5f);
    float4 gv = *(const float4*)(g  + t * 4);
    float4 bv = *(const float4*)(be + t * 4);
    float4 o;
    o.x = (v.x - mean) * rstd * gv.x + bv.x;
    o.y = (v.y - mean) * rstd * gv.y + bv.y;
    o.z = (v.z - mean) * rstd * gv.z + bv.z;
    o.w = (v.w - mean) * rstd * gv.w + bv.w;
    *(float4*)(out + (size_t)row * Dm + t * 4) = o;
}

// ---------------- generic tiled SGEMM (NN): C = A@B (+bias)(+res)(relu) -----
// A [M,K] row-major lda, B [K,N] row-major ldb, C [M,N] row-major ldc.
// All dims exact multiples of the tile sizes (true for this problem).
#define F_BIAS 1
#define F_RES  2
#define F_RELU 4

template<int BM, int BN, int BK, int TM, int TN, int FLAGS>
__global__ __launch_bounds__(256) void sgemm_k(
    const float* __restrict__ A, int lda,
    const float* __restrict__ B, int ldb,
    const float* __restrict__ bias,
    const float* __restrict__ Res,
    float* __restrict__ C, int ldc, int K)
{
    constexpr int NT = (BM / TM) * (BN / TN);
    static_assert(NT == 256, "expect 256 threads");
    __shared__ float As[BK][BM];
    __shared__ float Bs[BK][BN];
    const int tid = threadIdx.x;
    const int tx  = tid % (BN / TN);
    const int ty  = tid / (BN / TN);
    const int bm = blockIdx.y, bn = blockIdx.x;
    const float* Ab = A + (size_t)bm * BM * lda;
    const float* Bb = B + (size_t)bn * BN;

    float acc[TM][TN];
    #pragma unroll
    for (int i = 0; i < TM; i++)
        #pragma unroll
        for (int j = 0; j < TN; j++) acc[i][j] = 0.f;

    for (int k0 = 0; k0 < K; k0 += BK) {
        #pragma unroll
        for (int i = tid * 4; i < BM * BK; i += NT * 4) {
            const int r = i / BK, c = i % BK;
            float4 v4 = *(const float4*)(Ab + (size_t)r * lda + (k0 + c));
            As[c + 0][r] = v4.x; As[c + 1][r] = v4.y;
            As[c + 2][r] = v4.z; As[c + 3][r] = v4.w;
        }
        #pragma unroll
        for (int i = tid * 4; i < BK * BN; i += NT * 4) {
            const int r = i / BN, c = i % BN;
            *(float4*)&Bs[r][c] = *(const float4*)(Bb + (size_t)(k0 + r) * ldb + c);
        }
        __syncthreads();
        #pragma unroll
        for (int k = 0; k < BK; k++) {
            float a[TM], bb[TN];
            #pragma unroll
            for (int i = 0; i < TM; i += 4) *(float4*)&a[i]  = *(const float4*)&As[k][ty * TM + i];
            #pragma unroll
            for (int j = 0; j < TN; j += 4) *(float4*)&bb[j] = *(const float4*)&Bs[k][tx * TN + j];
            #pragma unroll
            for (int i = 0; i < TM; i++)
                #pragma unroll
                for (int j = 0; j < TN; j++) acc[i][j] = fmaf(a[i], bb[j], acc[i][j]);
        }
        __syncthreads();
    }
    const int row0 = bm * BM + ty * TM;
    const int col0 = bn * BN + tx * TN;
    #pragma unroll
    for (int i = 0; i < TM; i++) {
        const int row = row0 + i;
        #pragma unroll
        for (int j = 0; j < TN; j += 4) {
            float4 v;
            v.x = acc[i][j]; v.y = acc[i][j+1]; v.z = acc[i][j+2]; v.w = acc[i][j+3];
            if (FLAGS & F_BIAS) {
                float4 b4 = *(const float4*)(bias + col0 + j);
                v.x += b4.x; v.y += b4.y; v.z += b4.z; v.w += b4.w;
            }
            if (FLAGS & F_RES) {
                float4 r4 = *(const float4*)(Res + (size_t)row * ldc + col0 + j);
                v.x += r4.x; v.y += r4.y; v.z += r4.z; v.w += r4.w;
            }
            if (FLAGS & F_RELU) {
                v.x = fmaxf(v.x, 0.f); v.y = fmaxf(v.y, 0.f);
                v.z = fmaxf(v.z, 0.f); v.w = fmaxf(v.w, 0.f);
            }
            *(float4*)(C + (size_t)row * ldc + col0 + j) = v;
        }
    }
}

// ---------------- attention scores: S = scale * Q @ K^T (causal blocks) -----
// per (b,h): Q,K are [S, DKk] with row stride Dm. 128x128 tiles, skip bn>bm.
__global__ __launch_bounds__(256) void attn_scores_k(
    const float* __restrict__ Q, const float* __restrict__ Kmat, float* __restrict__ Sc)
{
    const int bm = blockIdx.y, bn = blockIdx.x;
    if (bn > bm) return;                       // fully masked block
    const int bh = blockIdx.z;
    const int b = bh >> 4, h = bh & 15;
    const float* Qb = Q    + (size_t)b * Ssz * Dm + h * DKk + (size_t)bm * 128 * Dm;
    const float* Kb = Kmat + (size_t)b * Ssz * Dm + h * DKk + (size_t)bn * 128 * Dm;
    float* Cb = Sc + (size_t)bh * Ssz * Ssz;

    __shared__ float As[8][128], Bs[8][128];
    const int tid = threadIdx.x;
    const int tx = tid & 15, ty = tid >> 4;
    const int lrow = tid >> 1, lcol = (tid & 1) * 4;

    float acc[8][8];
    #pragma unroll
    for (int i = 0; i < 8; i++)
        #pragma unroll
        for (int j = 0; j < 8; j++) acc[i][j] = 0.f;

    #pragma unroll
    for (int k0 = 0; k0 < DKk; k0 += 8) {
        float4 a4 = *(const float4*)(Qb + (size_t)lrow * Dm + k0 + lcol);
        float4 b4 = *(const float4*)(Kb + (size_t)lrow * Dm + k0 + lcol);
        As[lcol+0][lrow] = a4.x; As[lcol+1][lrow] = a4.y;
        As[lcol+2][lrow] = a4.z; As[lcol+3][lrow] = a4.w;
        Bs[lcol+0][lrow] = b4.x; Bs[lcol+1][lrow] = b4.y;
        Bs[lcol+2][lrow] = b4.z; Bs[lcol+3][lrow] = b4.w;
        __syncthreads();
        #pragma unroll
        for (int k = 0; k < 8; k++) {
            float a[8], bb[8];
            #pragma unroll
            for (int i = 0; i < 8; i += 4) *(float4*)&a[i]  = *(const float4*)&As[k][ty*8 + i];
            #pragma unroll
            for (int j = 0; j < 8; j += 4) *(float4*)&bb[j] = *(const float4*)&Bs[k][tx*8 + j];
            #pragma unroll
            for (int i = 0; i < 8; i++)
                #pragma unroll
                for (int j = 0; j < 8; j++) acc[i][j] = fmaf(a[i], bb[j], acc[i][j]);
        }
        __syncthreads();
    }
    const float scale = 0.125f;                // 1/sqrt(64)
    #pragma unroll
    for (int i = 0; i < 8; i++) {
        const int q = bm * 128 + ty * 8 + i;
        #pragma unroll
        for (int j = 0; j < 8; j += 4) {
            float4 v;
            v.x = acc[i][j]   * scale; v.y = acc[i][j+1] * scale;
            v.z = acc[i][j+2] * scale; v.w = acc[i][j+3] * scale;
            *(float4*)(Cb + (size_t)q * Ssz + bn * 128 + tx * 8 + j) = v;
        }
    }
}

// ---------------- causal softmax: warp per row -------------------------------
// writes normalized probs for k<=q, zeros for q<k<kend (64-aligned block end)
__global__ __launch_bounds__(256) void softmax_k(float* __restrict__ Sc)
{
    const int warp = threadIdx.x >> 5, lane = threadIdx.x & 31;
    const int row = blockIdx.x * 8 + warp;          // 0..B*H*S-1
    const int bh = row >> 10, q = row & 1023;
    float* r = Sc + (size_t)bh * Ssz * Ssz + (size_t)q * Ssz;
    const int n = q + 1;
    float vals[32];
    float m = -3.0e38f;
    #pragma unroll
    for (int i = 0; i < 32; i++) {
        const int k = lane + i * 32;
        float v = (k < n) ? r[k] : -3.0e38f;
        vals[i] = v; m = fmaxf(m, v);
    }
    #pragma unroll
    for (int off = 16; off; off >>= 1) m = fmaxf(m, __shfl_xor_sync(0xffffffffu, m, off));
    float s = 0.f;
    #pragma unroll
    for (int i = 0; i < 32; i++) { float e = __expf(vals[i] - m); vals[i] = e; s += e; }
    #pragma unroll
    for (int off = 16; off; off >>= 1) s += __shfl_xor_sync(0xffffffffu, s, off);
    const float inv = 1.0f / s;
    const int kend = ((q >> 6) + 1) << 6;
    #pragma unroll
    for (int i = 0; i < 32; i++) {
        const int k = lane + i * 32;
        if (k < kend) r[k] = (k < n) ? vals[i] * inv : 0.f;
    }
}

// ---------------- O = P @ V per (b,h): [S,S]@[S,DKk], K-loop truncated -------
__global__ __launch_bounds__(256) void attn_av_k(
    const float* __restrict__ P, const float* __restrict__ Vm, float* __restrict__ O)
{
    const int bh = blockIdx.z, b = bh >> 4, h = bh & 15;
    const int bm = blockIdx.x;                      // 0..15 (64-row tiles)
    const float* Pb = P  + (size_t)bh * Ssz * Ssz + (size_t)bm * 64 * Ssz;
    const float* Vb = Vm + (size_t)b * Ssz * Dm + h * DKk;
    float* Ob       = O  + (size_t)b * Ssz * Dm + h * DKk + (size_t)bm * 64 * Dm;
    const int Kmax = (bm + 1) * 64;                 // causal: probs zero beyond

    __shared__ float As[16][64], Bs[16][64];
    const int tid = threadIdx.x;
    const int tx = tid & 15, ty = tid >> 4;
    const int arow = tid >> 2,  acol = (tid & 3) * 4;
    const int brow = tid >> 4,  bcol = (tid & 15) * 4;

    float acc[4][4];
    #pragma unroll
    for (int i = 0; i < 4; i++)
        #pragma unroll
        for (int j = 0; j < 4; j++) acc[i][j] = 0.f;

    for (int k0 = 0; k0 < Kmax; k0 += 16) {
        float4 a4 = *(const float4*)(Pb + (size_t)arow * Ssz + k0 + acol);
        float4 b4 = *(const float4*)(Vb + (size_t)(k0 + brow) * Dm + bcol);
        As[acol+0][arow] = a4.x; As[acol+1][arow] = a4.y;
        As[acol+2][arow] = a4.z; As[acol+3][arow] = a4.w;
        *(float4*)&Bs[brow][bcol] = b4;
        __syncthreads();
        #pragma unroll
        for (int k = 0; k < 16; k++) {
            float a[4], bb[4];
            *(float4*)a  = *(const float4*)&As[k][ty * 4];
            *(float4*)bb = *(const float4*)&Bs[k][tx * 4];
            #pragma unroll
            for (int i = 0; i < 4; i++)
                #pragma unroll
                for (int j = 0; j < 4; j++) acc[i][j] = fmaf(a[i], bb[j], acc[i][j]);
        }
        __syncthreads();
    }
    #pragma unroll
    for (int i = 0; i < 4; i++) {
        float4 v; v.x = acc[i][0]; v.y = acc[i][1]; v.z = acc[i][2]; v.w = acc[i][3];
        *(float4*)(Ob + (size_t)(ty * 4 + i) * Dm + tx * 4) = v;
    }
}

// ---------------- driver -----------------------------------------------------
extern "C" void kernel_launch(void* const* d_in, const int* in_sizes, int n_in,
                              void* d_out, int out_size)
{
    const int*   ids  = (const int*)  d_in[0];
    const float* tok  = (const float*)d_in[1];
    const float* pos  = (const float*)d_in[2];
    const float* Wq   = (const float*)d_in[3];
    const float* bq   = (const float*)d_in[4];
    const float* Wk   = (const float*)d_in[5];
    const float* bk   = (const float*)d_in[6];
    const float* Wv   = (const float*)d_in[7];
    const float* bv   = (const float*)d_in[8];
    const float* Wo   = (const float*)d_in[9];
    const float* bo   = (const float*)d_in[10];
    const float* W1   = (const float*)d_in[11];
    const float* b1   = (const float*)d_in[12];
    const float* W2   = (const float*)d_in[13];
    const float* b2   = (const float*)d_in[14];
    const float* ln1g = (const float*)d_in[15];
    const float* ln1b = (const float*)d_in[16];
    const float* ln2g = (const float*)d_in[17];
    const float* ln2b = (const float*)d_in[18];
    const float* lnfg = (const float*)d_in[19];
    const float* lnfb = (const float*)d_in[20];
    const float* Wout = (const float*)d_in[21];
    const float* bout = (const float*)d_in[22];
    float* out = (float*)d_out;

    float *x, *h, *q, *k, *v, *o, *ff, *sc;
    cudaGetSymbolAddress((void**)&x,  g_x);
    cudaGetSymbolAddress((void**)&h,  g_h);
    cudaGetSymbolAddress((void**)&q,  g_q);
    cudaGetSymbolAddress((void**)&k,  g_k);
    cudaGetSymbolAddress((void**)&v,  g_v);
    cudaGetSymbolAddress((void**)&o,  g_o);
    cudaGetSymbolAddress((void**)&ff, g_ff);
    cudaGetSymbolAddress((void**)&sc, g_sc);

    embed_k<<<TOK, 256>>>(ids, tok, pos, x);

    const dim3 gProj(Dm / 64,  TOK / 128);   // N=1024 GEMMs: 128x64 tiles, 256 blocks
    const dim3 gFfn1(Ff / 128, TOK / 128);   // N=4096: 128x128 tiles, 512 blocks
    const dim3 gLogit(Vv / 128, TOK / 128);  // N=32000: 4000 blocks
    const dim3 gScore(Ssz / 128, Ssz / 128, Bsz * Hh);
    const dim3 gAv(Ssz / 64, 1, Bsz * Hh);

    for (int l = 0; l < Ll; l++) {
        const size_t oD  = (size_t)l * Dm * Dm;
        const size_t oF  = (size_t)l * Dm * Ff;
        const size_t oDb = (size_t)l * Dm;
        const size_t oFb = (size_t)l * Ff;

        layernorm_k<<<TOK, 256>>>(x, ln1g + oDb, ln1b + oDb, h);
        sgemm_k<128,64,8,8,4,F_BIAS><<<gProj, 256>>>(h, Dm, Wq + oD, Dm, bq + oDb, nullptr, q, Dm, Dm);
        sgemm_k<128,64,8,8,4,F_BIAS><<<gProj, 256>>>(h, Dm, Wk + oD, Dm, bk + oDb, nullptr, k, Dm, Dm);
        sgemm_k<128,64,8,8,4,F_BIAS><<<gProj, 256>>>(h, Dm, Wv + oD, Dm, bv + oDb, nullptr, v, Dm, Dm);

        attn_scores_k<<<gScore, 256>>>(q, k, sc);
        softmax_k<<<(Bsz * Hh * Ssz) / 8, 256>>>(sc);
        attn_av_k<<<gAv, 256>>>(sc, v, o);

        sgemm_k<128,64,8,8,4,F_BIAS|F_RES><<<gProj, 256>>>(o, Dm, Wo + oD, Dm, bo + oDb, x, x, Dm, Dm);

        layernorm_k<<<TOK, 256>>>(x, ln2g + oDb, ln2b + oDb, h);
        sgemm_k<128,128,8,8,8,F_BIAS|F_RELU><<<gFfn1, 256>>>(h, Dm, W1 + oF, Ff, b1 + oFb, nullptr, ff, Ff, Dm);
        sgemm_k<128,64,8,8,4,F_BIAS|F_RES><<<gProj, 256>>>(ff, Ff, W2 + oF, Dm, b2 + oDb, x, x, Dm, Ff);
    }

    layernorm_k<<<TOK, 256>>>(x, lnfg, lnfb, h);
    sgemm_k<128,128,8,8,8,F_BIAS><<<gLogit, 256>>>(h, Dm, Wout, Vv, bout, nullptr, out, Vv, Dm);
}